// round 4
// baseline (speedup 1.0000x reference)
#include <cuda_runtime.h>
#include <math.h>

#define BB 4
#define SS 2048
#define DM 1024
#define NH 16
#define DK 64
#define MM (BB*SS)   // 8192

// Scratch (allocation-free): __device__ globals
__device__ float g_q[BB*NH*SS*DK];      // [b,h,s,dk]
__device__ float g_k[BB*NH*SS*DK];
__device__ float g_v[BB*NH*SS*DK];
__device__ float g_att[MM*DM];          // [b,s,d] row-major

// ---------------------------------------------------------------------------
// SGEMM: C = A @ W^T.  A: [8192,1024] row-major, W: [1024,1024] row-major.
// scatter=1: write to [b,h,s,dk] layout; scatter=0: plain [M,N] row-major.
// Tile 64x64, BK=16, 256 threads, 4x4 per thread.
// ---------------------------------------------------------------------------
__global__ __launch_bounds__(256) void sgemm_kernel(const float* __restrict__ A,
                                                    const float* __restrict__ W,
                                                    float* __restrict__ C,
                                                    int scatter)
{
    __shared__ float As[16][68];   // pad to 68 -> conflict-free transposed stores
    __shared__ float Bs[16][68];

    const int t  = threadIdx.x;
    const int tx = t & 15, ty = t >> 4;
    const int m0 = blockIdx.y * 64, n0 = blockIdx.x * 64;
    const int lr = t >> 2;            // 0..63: row within tile
    const int lk = (t & 3) << 2;      // 0,4,8,12: k offset (float4)

    float c[4][4] = {};

    const float* Arow = A + (size_t)(m0 + lr) * DM + lk;
    const float* Wrow = W + (size_t)(n0 + lr) * DM + lk;

    for (int k0 = 0; k0 < DM; k0 += 16) {
        float4 av = *(const float4*)(Arow + k0);
        float4 bv = *(const float4*)(Wrow + k0);
        As[lk+0][lr] = av.x; As[lk+1][lr] = av.y; As[lk+2][lr] = av.z; As[lk+3][lr] = av.w;
        Bs[lk+0][lr] = bv.x; Bs[lk+1][lr] = bv.y; Bs[lk+2][lr] = bv.z; Bs[lk+3][lr] = bv.w;
        __syncthreads();
#pragma unroll
        for (int k = 0; k < 16; k++) {
            float4 a4 = *(const float4*)&As[k][ty * 4];
            float4 b4 = *(const float4*)&Bs[k][tx * 4];
            float a[4] = {a4.x, a4.y, a4.z, a4.w};
            float b[4] = {b4.x, b4.y, b4.z, b4.w};
#pragma unroll
            for (int i = 0; i < 4; i++)
#pragma unroll
                for (int j = 0; j < 4; j++)
                    c[i][j] += a[i] * b[j];
        }
        __syncthreads();
    }

#pragma unroll
    for (int i = 0; i < 4; i++) {
        int m = m0 + ty * 4 + i;
#pragma unroll
        for (int j = 0; j < 4; j++) {
            int n = n0 + tx * 4 + j;
            if (scatter) {
                int b = m >> 11, s = m & 2047, h = n >> 6, d = n & 63;
                C[(((size_t)((b << 4) + h)) * SS + s) * DK + d] = c[i][j];
            } else {
                C[(size_t)m * DM + n] = c[i][j];
            }
        }
    }
}

// ---------------------------------------------------------------------------
// RoPE in-place on [bh, s, dk] tensor. One thread per (even,odd) pair.
// ---------------------------------------------------------------------------
__global__ void rope_kernel(float* __restrict__ X)
{
    int idx = blockIdx.x * 256 + threadIdx.x;
    // total = 64 * 2048 * 32
    int i  = idx & 31;
    int s  = (idx >> 5) & 2047;
    int bh = idx >> 16;
    float inv = powf(10000.0f, -(2.0f * (float)i) / 64.0f);
    float ang = (float)s * inv;
    float sn, cs;
    sincosf(ang, &sn, &cs);
    float* p = X + ((size_t)bh * SS + s) * DK + 2 * i;
    float x1 = p[0], x2 = p[1];
    p[0] = x1 * cs - x2 * sn;
    p[1] = x1 * sn + x2 * cs;
}

// ---------------------------------------------------------------------------
// Causal flash attention, fp32.
// Grid: (qblock=16, bh=64). Block: 128 threads, 1 query row per thread.
// K/V tiles of 32 rows staged in smem; online softmax; causal tile truncation.
// Output written in [b,s,d] row-major layout (ready for o_proj GEMM).
// ---------------------------------------------------------------------------
__global__ __launch_bounds__(128) void attn_kernel(const float* __restrict__ Q,
                                                   const float* __restrict__ K,
                                                   const float* __restrict__ V,
                                                   float* __restrict__ O)
{
    __shared__ float4 Ks[32 * 16];
    __shared__ float4 Vs[32 * 16];

    const int tid = threadIdx.x;
    const int bh  = blockIdx.y;
    const int h   = bh & 15;
    const int b   = bh >> 4;
    const int qi  = blockIdx.x * 128 + tid;

    const float4* Qr = (const float4*)(Q + ((size_t)bh * SS + qi) * DK);
    const float4* Kb = (const float4*)(K + (size_t)bh * SS * DK);
    const float4* Vb = (const float4*)(V + (size_t)bh * SS * DK);

    float4 q4[16];
#pragma unroll
    for (int i = 0; i < 16; i++) q4[i] = Qr[i];

    float4 acc[16] = {};
    float mx = -1e30f, l = 0.0f;

    const int ntiles = blockIdx.x * 4 + 4;   // covers kv in [0, qblock_end]

    for (int t = 0; t < ntiles; t++) {
        const int kv0 = t * 32;
        __syncthreads();
        for (int i = tid; i < 512; i += 128) {
            Ks[i] = Kb[kv0 * 16 + i];
            Vs[i] = Vb[kv0 * 16 + i];
        }
        __syncthreads();

        float sc[32];
#pragma unroll
        for (int j = 0; j < 32; j++) {
            float d = 0.0f;
#pragma unroll
            for (int c = 0; c < 16; c++) {
                float4 k4 = Ks[j * 16 + c];
                d += q4[c].x * k4.x + q4[c].y * k4.y + q4[c].z * k4.z + q4[c].w * k4.w;
            }
            sc[j] = (kv0 + j <= qi) ? d * 0.125f : -1e30f;
        }

        float mt = mx;
#pragma unroll
        for (int j = 0; j < 32; j++) mt = fmaxf(mt, sc[j]);

        float alpha = __expf(mx - mt);
        l *= alpha;
#pragma unroll
        for (int j = 0; j < 32; j++) {
            float p = __expf(sc[j] - mt);
            l += p;
            sc[j] = p;
        }
#pragma unroll
        for (int c = 0; c < 16; c++) {
            acc[c].x *= alpha; acc[c].y *= alpha; acc[c].z *= alpha; acc[c].w *= alpha;
        }
#pragma unroll
        for (int j = 0; j < 32; j++) {
            float p = sc[j];
#pragma unroll
            for (int c = 0; c < 16; c++) {
                float4 v4 = Vs[j * 16 + c];
                acc[c].x += p * v4.x; acc[c].y += p * v4.y;
                acc[c].z += p * v4.z; acc[c].w += p * v4.w;
            }
        }
        mx = mt;
    }

    float invl = 1.0f / l;
    float4* Orow = (float4*)(O + ((size_t)b * SS + qi) * DM + h * DK);
#pragma unroll
    for (int c = 0; c < 16; c++) {
        float4 o = acc[c];
        o.x *= invl; o.y *= invl; o.z *= invl; o.w *= invl;
        Orow[c] = o;
    }
}

// ---------------------------------------------------------------------------
extern "C" void kernel_launch(void* const* d_in, const int* in_sizes, int n_in,
                              void* d_out, int out_size)
{
    const float* x  = (const float*)d_in[0];
    const float* qw = (const float*)d_in[1];
    const float* kw = (const float*)d_in[2];
    const float* vw = (const float*)d_in[3];
    const float* ow = (const float*)d_in[4];
    float* out = (float*)d_out;

    float *q, *k, *v, *att;
    cudaGetSymbolAddress((void**)&q,   g_q);
    cudaGetSymbolAddress((void**)&k,   g_k);
    cudaGetSymbolAddress((void**)&v,   g_v);
    cudaGetSymbolAddress((void**)&att, g_att);

    dim3 gg(DM / 64, MM / 64);   // (16, 128)

    sgemm_kernel<<<gg, 256>>>(x, qw, q, 1);
    sgemm_kernel<<<gg, 256>>>(x, kw, k, 1);
    sgemm_kernel<<<gg, 256>>>(x, vw, v, 1);

    const int nrope = BB * NH * SS * 32;     // 4.19M pairs
    rope_kernel<<<nrope / 256, 256>>>(q);
    rope_kernel<<<nrope / 256, 256>>>(k);

    attn_kernel<<<dim3(16, 64), 128>>>(q, k, v, att);

    sgemm_kernel<<<gg, 256>>>(att, ow, out, 0);
}

// round 9
// speedup vs baseline: 1.5296x; 1.5296x over previous
#include <cuda_runtime.h>
#include <math.h>
#include <cstdint>

#define BB 4
#define SS 2048
#define DM 1024
#define NH 16
#define DK 64
#define MM (BB*SS)   // 8192

// Scratch (allocation-free): __device__ globals
__device__ float g_q[BB*NH*SS*DK];      // [b,h,s,dk]
__device__ float g_k[BB*NH*SS*DK];
__device__ float g_v[BB*NH*SS*DK];
__device__ float g_att[MM*DM];          // [b,s,d] row-major

__device__ __forceinline__ uint32_t f2tf32(float f) {
    uint32_t r;
    asm("cvt.rna.tf32.f32 %0, %1;" : "=r"(r) : "f"(f));
    return r;
}

__device__ __forceinline__ void mma_tf32(float* c, const uint32_t* a, const uint32_t* b) {
    asm volatile(
        "mma.sync.aligned.m16n8k8.row.col.f32.tf32.tf32.f32 "
        "{%0,%1,%2,%3}, {%4,%5,%6,%7}, {%8,%9}, {%0,%1,%2,%3};"
        : "+f"(c[0]), "+f"(c[1]), "+f"(c[2]), "+f"(c[3])
        : "r"(a[0]), "r"(a[1]), "r"(a[2]), "r"(a[3]), "r"(b[0]), "r"(b[1]));
}

// ===========================================================================
// Tensor-core GEMM via mma.sync tf32: C = A @ W^T.
// A:[M,1024] row-major, W:[1024,1024] row-major (both K contiguous).
// Block 128x128, BK=32, 256 threads, warp grid 4(m) x 2(n), warp tile 32x64.
// scatter=1 -> [b,h,s,dk] layout; scatter=0 -> [M,N] row-major.
// ===========================================================================
#define SPITCH 36   // 32 + 4 pad: bank = (4*row + col) % 32 bijective per warp

__global__ __launch_bounds__(256) void tgemm_kernel(const float* __restrict__ A,
                                                    const float* __restrict__ W,
                                                    float* __restrict__ C,
                                                    int scatter)
{
    __shared__ uint32_t As[128 * SPITCH];
    __shared__ uint32_t Bs[128 * SPITCH];

    const int tid = threadIdx.x;
    const int wid = tid >> 5, lid = tid & 31;
    const int gid = lid >> 2, tig = lid & 3;       // group id / thread-in-group
    const int wm = (wid & 3) * 32;                 // warp m offset
    const int wn = (wid >> 2) * 64;                // warp n offset
    const int m0 = blockIdx.y * 128, n0 = blockIdx.x * 128;

    const int ldrow = tid >> 3;                    // staging: row 0..31 (x4 iters)
    const int ldc4  = tid & 7;                     // float4 index within 32-wide row

    float acc[2][8][4] = {};
    float4 pa[4], pb[4];

    // prefetch tile 0
#pragma unroll
    for (int i = 0; i < 4; i++) {
        int row = ldrow + i * 32;
        pa[i] = *(const float4*)(A + (size_t)(m0 + row) * DM + ldc4 * 4);
        pb[i] = *(const float4*)(W + (size_t)(n0 + row) * DM + ldc4 * 4);
    }

    for (int it = 0; it < DM / 32; ++it) {
        // stage current tile (fp32 -> tf32) into smem
#pragma unroll
        for (int i = 0; i < 4; i++) {
            int row = ldrow + i * 32;
            uint32_t off = row * SPITCH + ldc4 * 4;
            As[off+0] = f2tf32(pa[i].x); As[off+1] = f2tf32(pa[i].y);
            As[off+2] = f2tf32(pa[i].z); As[off+3] = f2tf32(pa[i].w);
            Bs[off+0] = f2tf32(pb[i].x); Bs[off+1] = f2tf32(pb[i].y);
            Bs[off+2] = f2tf32(pb[i].z); Bs[off+3] = f2tf32(pb[i].w);
        }
        __syncthreads();

        // prefetch next tile (overlaps with compute below)
        if (it + 1 < DM / 32) {
            int kk = (it + 1) * 32;
#pragma unroll
            for (int i = 0; i < 4; i++) {
                int row = ldrow + i * 32;
                pa[i] = *(const float4*)(A + (size_t)(m0 + row) * DM + kk + ldc4 * 4);
                pb[i] = *(const float4*)(W + (size_t)(n0 + row) * DM + kk + ldc4 * 4);
            }
        }

        // 4 k-steps of 8
#pragma unroll
        for (int ks = 0; ks < 4; ks++) {
            const int k0 = ks * 8;
            uint32_t a[2][4], b[8][2];
#pragma unroll
            for (int mt = 0; mt < 2; mt++) {
                int r = wm + mt * 16 + gid;
                a[mt][0] = As[r * SPITCH + k0 + tig];
                a[mt][1] = As[(r + 8) * SPITCH + k0 + tig];
                a[mt][2] = As[r * SPITCH + k0 + tig + 4];
                a[mt][3] = As[(r + 8) * SPITCH + k0 + tig + 4];
            }
#pragma unroll
            for (int nt = 0; nt < 8; nt++) {
                int cn = wn + nt * 8 + gid;
                b[nt][0] = Bs[cn * SPITCH + k0 + tig];
                b[nt][1] = Bs[cn * SPITCH + k0 + tig + 4];
            }
#pragma unroll
            for (int mt = 0; mt < 2; mt++)
#pragma unroll
                for (int nt = 0; nt < 8; nt++)
                    mma_tf32(acc[mt][nt], a[mt], b[nt]);
        }
        __syncthreads();
    }

    // epilogue: c0,c1 -> (row, n..n+1); c2,c3 -> (row+8, n..n+1)
#pragma unroll
    for (int mt = 0; mt < 2; mt++) {
#pragma unroll
        for (int nt = 0; nt < 8; nt++) {
            int m = m0 + wm + mt * 16 + gid;
            int n = n0 + wn + nt * 8 + 2 * tig;
            float2 lo = make_float2(acc[mt][nt][0], acc[mt][nt][1]);
            float2 hi = make_float2(acc[mt][nt][2], acc[mt][nt][3]);
            if (scatter) {
                int h = n >> 6, d = n & 63;
                int b1 = m >> 11, s1 = m & 2047;
                int m2 = m + 8;
                int b2 = m2 >> 11, s2 = m2 & 2047;
                *(float2*)(C + (((size_t)((b1 << 4) + h)) * SS + s1) * DK + d) = lo;
                *(float2*)(C + (((size_t)((b2 << 4) + h)) * SS + s2) * DK + d) = hi;
            } else {
                *(float2*)(C + (size_t)m * DM + n) = lo;
                *(float2*)(C + (size_t)(m + 8) * DM + n) = hi;
            }
        }
    }
}

// ---------------------------------------------------------------------------
// RoPE in-place on [bh, s, dk] tensor. One thread per (even,odd) pair.
// ---------------------------------------------------------------------------
__global__ void rope_kernel(float* __restrict__ X)
{
    int idx = blockIdx.x * 256 + threadIdx.x;
    int i  = idx & 31;
    int s  = (idx >> 5) & 2047;
    int bh = idx >> 16;
    float inv = powf(10000.0f, -(2.0f * (float)i) / 64.0f);
    float ang = (float)s * inv;
    float sn, cs;
    sincosf(ang, &sn, &cs);
    float* p = X + ((size_t)bh * SS + s) * DK + 2 * i;
    float x1 = p[0], x2 = p[1];
    p[0] = x1 * cs - x2 * sn;
    p[1] = x1 * sn + x2 * cs;
}

// ---------------------------------------------------------------------------
// Causal flash attention, fp32 (unchanged this round).
// ---------------------------------------------------------------------------
__global__ __launch_bounds__(128) void attn_kernel(const float* __restrict__ Q,
                                                   const float* __restrict__ K,
                                                   const float* __restrict__ V,
                                                   float* __restrict__ O)
{
    __shared__ float4 Ks[32 * 16];
    __shared__ float4 Vs[32 * 16];

    const int tid = threadIdx.x;
    const int bh  = blockIdx.y;
    const int h   = bh & 15;
    const int b   = bh >> 4;
    const int qi  = blockIdx.x * 128 + tid;

    const float4* Qr = (const float4*)(Q + ((size_t)bh * SS + qi) * DK);
    const float4* Kb = (const float4*)(K + (size_t)bh * SS * DK);
    const float4* Vb = (const float4*)(V + (size_t)bh * SS * DK);

    float4 q4[16];
#pragma unroll
    for (int i = 0; i < 16; i++) q4[i] = Qr[i];

    float4 acc[16] = {};
    float mx = -1e30f, l = 0.0f;

    const int ntiles = blockIdx.x * 4 + 4;

    for (int t = 0; t < ntiles; t++) {
        const int kv0 = t * 32;
        __syncthreads();
        for (int i = tid; i < 512; i += 128) {
            Ks[i] = Kb[kv0 * 16 + i];
            Vs[i] = Vb[kv0 * 16 + i];
        }
        __syncthreads();

        float sc[32];
#pragma unroll
        for (int j = 0; j < 32; j++) {
            float d = 0.0f;
#pragma unroll
            for (int c = 0; c < 16; c++) {
                float4 k4 = Ks[j * 16 + c];
                d += q4[c].x * k4.x + q4[c].y * k4.y + q4[c].z * k4.z + q4[c].w * k4.w;
            }
            sc[j] = (kv0 + j <= qi) ? d * 0.125f : -1e30f;
        }

        float mt = mx;
#pragma unroll
        for (int j = 0; j < 32; j++) mt = fmaxf(mt, sc[j]);

        float alpha = __expf(mx - mt);
        l *= alpha;
#pragma unroll
        for (int j = 0; j < 32; j++) {
            float p = __expf(sc[j] - mt);
            l += p;
            sc[j] = p;
        }
#pragma unroll
        for (int c = 0; c < 16; c++) {
            acc[c].x *= alpha; acc[c].y *= alpha; acc[c].z *= alpha; acc[c].w *= alpha;
        }
#pragma unroll
        for (int j = 0; j < 32; j++) {
            float p = sc[j];
#pragma unroll
            for (int c = 0; c < 16; c++) {
                float4 v4 = Vs[j * 16 + c];
                acc[c].x += p * v4.x; acc[c].y += p * v4.y;
                acc[c].z += p * v4.z; acc[c].w += p * v4.w;
            }
        }
        mx = mt;
    }

    float invl = 1.0f / l;
    float4* Orow = (float4*)(O + ((size_t)b * SS + qi) * DM + h * DK);
#pragma unroll
    for (int c = 0; c < 16; c++) {
        float4 o = acc[c];
        o.x *= invl; o.y *= invl; o.z *= invl; o.w *= invl;
        Orow[c] = o;
    }
}

// ---------------------------------------------------------------------------
extern "C" void kernel_launch(void* const* d_in, const int* in_sizes, int n_in,
                              void* d_out, int out_size)
{
    const float* x  = (const float*)d_in[0];
    const float* qw = (const float*)d_in[1];
    const float* kw = (const float*)d_in[2];
    const float* vw = (const float*)d_in[3];
    const float* ow = (const float*)d_in[4];
    float* out = (float*)d_out;

    float *q, *k, *v, *att;
    cudaGetSymbolAddress((void**)&q,   g_q);
    cudaGetSymbolAddress((void**)&k,   g_k);
    cudaGetSymbolAddress((void**)&v,   g_v);
    cudaGetSymbolAddress((void**)&att, g_att);

    dim3 gg(DM / 128, MM / 128);   // (8, 64) = 512 CTAs

    tgemm_kernel<<<gg, 256>>>(x, qw, q, 1);
    tgemm_kernel<<<gg, 256>>>(x, kw, k, 1);
    tgemm_kernel<<<gg, 256>>>(x, vw, v, 1);

    const int nrope = BB * NH * SS * 32;
    rope_kernel<<<nrope / 256, 256>>>(q);
    rope_kernel<<<nrope / 256, 256>>>(k);

    attn_kernel<<<dim3(16, 64), 128>>>(q, k, v, att);

    tgemm_kernel<<<gg, 256>>>(att, ow, out, 0);
}

// round 11
// speedup vs baseline: 3.2382x; 2.1170x over previous
#include <cuda_runtime.h>
#include <math.h>
#include <cstdint>

#define BB 4
#define SS 2048
#define DM 1024
#define NH 16
#define DK 64
#define MM (BB*SS)   // 8192

// Scratch (allocation-free): __device__ globals
__device__ float g_q[BB*NH*SS*DK];      // [b,h,s,dk]
__device__ float g_k[BB*NH*SS*DK];
__device__ float g_v[BB*NH*SS*DK];
__device__ float g_att[MM*DM];          // [b,s,d] row-major

__device__ __forceinline__ uint32_t f2tf32(float f) {
    uint32_t r;
    asm("cvt.rna.tf32.f32 %0, %1;" : "=r"(r) : "f"(f));
    return r;
}

__device__ __forceinline__ void mma_tf32(float* c, const uint32_t* a, const uint32_t* b) {
    asm volatile(
        "mma.sync.aligned.m16n8k8.row.col.f32.tf32.tf32.f32 "
        "{%0,%1,%2,%3}, {%4,%5,%6,%7}, {%8,%9}, {%0,%1,%2,%3};"
        : "+f"(c[0]), "+f"(c[1]), "+f"(c[2]), "+f"(c[3])
        : "r"(a[0]), "r"(a[1]), "r"(a[2]), "r"(a[3]), "r"(b[0]), "r"(b[1]));
}

// ===========================================================================
// Tensor-core GEMM via mma.sync tf32: C = A @ W^T.  (unchanged, passing)
// ===========================================================================
#define SPITCH 36

__global__ __launch_bounds__(256) void tgemm_kernel(const float* __restrict__ A,
                                                    const float* __restrict__ W,
                                                    float* __restrict__ C,
                                                    int scatter)
{
    __shared__ uint32_t As[128 * SPITCH];
    __shared__ uint32_t Bs[128 * SPITCH];

    const int tid = threadIdx.x;
    const int wid = tid >> 5, lid = tid & 31;
    const int gid = lid >> 2, tig = lid & 3;
    const int wm = (wid & 3) * 32;
    const int wn = (wid >> 2) * 64;
    const int m0 = blockIdx.y * 128, n0 = blockIdx.x * 128;

    const int ldrow = tid >> 3;
    const int ldc4  = tid & 7;

    float acc[2][8][4] = {};
    float4 pa[4], pb[4];

#pragma unroll
    for (int i = 0; i < 4; i++) {
        int row = ldrow + i * 32;
        pa[i] = *(const float4*)(A + (size_t)(m0 + row) * DM + ldc4 * 4);
        pb[i] = *(const float4*)(W + (size_t)(n0 + row) * DM + ldc4 * 4);
    }

    for (int it = 0; it < DM / 32; ++it) {
#pragma unroll
        for (int i = 0; i < 4; i++) {
            int row = ldrow + i * 32;
            uint32_t off = row * SPITCH + ldc4 * 4;
            As[off+0] = f2tf32(pa[i].x); As[off+1] = f2tf32(pa[i].y);
            As[off+2] = f2tf32(pa[i].z); As[off+3] = f2tf32(pa[i].w);
            Bs[off+0] = f2tf32(pb[i].x); Bs[off+1] = f2tf32(pb[i].y);
            Bs[off+2] = f2tf32(pb[i].z); Bs[off+3] = f2tf32(pb[i].w);
        }
        __syncthreads();

        if (it + 1 < DM / 32) {
            int kk = (it + 1) * 32;
#pragma unroll
            for (int i = 0; i < 4; i++) {
                int row = ldrow + i * 32;
                pa[i] = *(const float4*)(A + (size_t)(m0 + row) * DM + kk + ldc4 * 4);
                pb[i] = *(const float4*)(W + (size_t)(n0 + row) * DM + kk + ldc4 * 4);
            }
        }

#pragma unroll
        for (int ks = 0; ks < 4; ks++) {
            const int k0 = ks * 8;
            uint32_t a[2][4], b[8][2];
#pragma unroll
            for (int mt = 0; mt < 2; mt++) {
                int r = wm + mt * 16 + gid;
                a[mt][0] = As[r * SPITCH + k0 + tig];
                a[mt][1] = As[(r + 8) * SPITCH + k0 + tig];
                a[mt][2] = As[r * SPITCH + k0 + tig + 4];
                a[mt][3] = As[(r + 8) * SPITCH + k0 + tig + 4];
            }
#pragma unroll
            for (int nt = 0; nt < 8; nt++) {
                int cn = wn + nt * 8 + gid;
                b[nt][0] = Bs[cn * SPITCH + k0 + tig];
                b[nt][1] = Bs[cn * SPITCH + k0 + tig + 4];
            }
#pragma unroll
            for (int mt = 0; mt < 2; mt++)
#pragma unroll
                for (int nt = 0; nt < 8; nt++)
                    mma_tf32(acc[mt][nt], a[mt], b[nt]);
        }
        __syncthreads();
    }

#pragma unroll
    for (int mt = 0; mt < 2; mt++) {
#pragma unroll
        for (int nt = 0; nt < 8; nt++) {
            int m = m0 + wm + mt * 16 + gid;
            int n = n0 + wn + nt * 8 + 2 * tig;
            float2 lo = make_float2(acc[mt][nt][0], acc[mt][nt][1]);
            float2 hi = make_float2(acc[mt][nt][2], acc[mt][nt][3]);
            if (scatter) {
                int h = n >> 6, d = n & 63;
                int b1 = m >> 11, s1 = m & 2047;
                int m2 = m + 8;
                int b2 = m2 >> 11, s2 = m2 & 2047;
                *(float2*)(C + (((size_t)((b1 << 4) + h)) * SS + s1) * DK + d) = lo;
                *(float2*)(C + (((size_t)((b2 << 4) + h)) * SS + s2) * DK + d) = hi;
            } else {
                *(float2*)(C + (size_t)m * DM + n) = lo;
                *(float2*)(C + (size_t)(m + 8) * DM + n) = hi;
            }
        }
    }
}

// ---------------------------------------------------------------------------
// RoPE in-place on [bh, s, dk] tensor.
// ---------------------------------------------------------------------------
__global__ void rope_kernel(float* __restrict__ X)
{
    int idx = blockIdx.x * 256 + threadIdx.x;
    int i  = idx & 31;
    int s  = (idx >> 5) & 2047;
    int bh = idx >> 16;
    float inv = powf(10000.0f, -(2.0f * (float)i) / 64.0f);
    float ang = (float)s * inv;
    float sn, cs;
    sincosf(ang, &sn, &cs);
    float* p = X + ((size_t)bh * SS + s) * DK + 2 * i;
    float x1 = p[0], x2 = p[1];
    p[0] = x1 * cs - x2 * sn;
    p[1] = x1 * sn + x2 * cs;
}

// ===========================================================================
// Tensor-core causal flash attention (3xTF32 for fp32-grade accuracy).
// Grid: (32 qtiles, 64 bh). Block 128 = 4 warps x 16 q-rows.
// KV tiles of 32; K/V split hi/lo at staging; Q frags hoisted split;
// P fragments built from S accumulators via shfl, split in registers.
// ===========================================================================
#define KP 68   // K smem pitch: B-frag bank = 4*gid+tig (bijective)
#define VP 72   // V smem pitch: B-frag bank = 8*tig+gid (bijective)

__global__ __launch_bounds__(128) void fattn_kernel(const float* __restrict__ Q,
                                                    const float* __restrict__ K,
                                                    const float* __restrict__ V,
                                                    float* __restrict__ O)
{
    __shared__ uint32_t Kh[32 * KP], Kl[32 * KP];
    __shared__ uint32_t Vh[32 * VP], Vl[32 * VP];

    const int tid = threadIdx.x, wid = tid >> 5, lid = tid & 31;
    const int gid = lid >> 2, tig = lid & 3;
    const int qt = 31 - blockIdx.x;          // heavy tiles first
    const int bh = blockIdx.y;
    const int h = bh & 15, b = bh >> 4;
    const int q0 = qt * 64;
    const int wrow = q0 + wid * 16 + gid;    // row0 of this thread (row1 = +8)

    const float* Qb = Q + (size_t)bh * SS * DK;
    const float* Kb = K + (size_t)bh * SS * DK;
    const float* Vb = V + (size_t)bh * SS * DK;

    // Hoist Q A-fragments (hi/lo) for all 8 dk k-steps
    uint32_t qh[8][4], ql[8][4];
    {
        const float* r0 = Qb + (size_t)wrow * DK;
        const float* r1 = r0 + 8 * DK;
#pragma unroll
        for (int ks = 0; ks < 8; ks++) {
            float f[4] = { r0[ks*8 + tig], r1[ks*8 + tig],
                           r0[ks*8 + tig + 4], r1[ks*8 + tig + 4] };
#pragma unroll
            for (int e = 0; e < 4; e++) {
                qh[ks][e] = f2tf32(f[e]);
                ql[ks][e] = f2tf32(f[e] - __uint_as_float(qh[ks][e]));
            }
        }
    }

    float oacc[8][4] = {};
    float m0 = -1e30f, m1 = -1e30f, l0 = 0.0f, l1 = 0.0f;

    const int ntiles = 2 * qt + 2;
    for (int t = 0; t < ntiles; t++) {
        const int kv0 = t * 32;
        const bool domask = (t >= 2 * qt);
        __syncthreads();
        // Stage K,V tile: fp32 -> (hi,lo) tf32 pairs
#pragma unroll
        for (int j = 0; j < 4; j++) {
            int idx = tid + j * 128;
            int kv = idx >> 4, c4 = idx & 15;
            float4 kf = *(const float4*)(Kb + (size_t)(kv0 + kv) * DK + c4 * 4);
            float4 vf = *(const float4*)(Vb + (size_t)(kv0 + kv) * DK + c4 * 4);
            float kk[4] = {kf.x, kf.y, kf.z, kf.w};
            float vv[4] = {vf.x, vf.y, vf.z, vf.w};
            uint4 KH, KL, VH, VL;
            uint32_t* kh = (uint32_t*)&KH; uint32_t* kl = (uint32_t*)&KL;
            uint32_t* vh = (uint32_t*)&VH; uint32_t* vl = (uint32_t*)&VL;
#pragma unroll
            for (int e = 0; e < 4; e++) {
                kh[e] = f2tf32(kk[e]);
                kl[e] = f2tf32(kk[e] - __uint_as_float(kh[e]));
                vh[e] = f2tf32(vv[e]);
                vl[e] = f2tf32(vv[e] - __uint_as_float(vh[e]));
            }
            *(uint4*)&Kh[kv * KP + c4 * 4] = KH;
            *(uint4*)&Kl[kv * KP + c4 * 4] = KL;
            *(uint4*)&Vh[kv * VP + c4 * 4] = VH;
            *(uint4*)&Vl[kv * VP + c4 * 4] = VL;
        }
        __syncthreads();

        // ---- S = Q K^T (3x tf32) ----
        float sfr[4][4] = {};
#pragma unroll
        for (int ks = 0; ks < 8; ks++) {
#pragma unroll
            for (int nt = 0; nt < 4; nt++) {
                int r = (nt * 8 + gid) * KP + ks * 8 + tig;
                uint32_t BH[2] = { Kh[r], Kh[r + 4] };
                uint32_t BL[2] = { Kl[r], Kl[r + 4] };
                mma_tf32(sfr[nt], qh[ks], BH);
                mma_tf32(sfr[nt], qh[ks], BL);
                mma_tf32(sfr[nt], ql[ks], BH);
            }
        }

        // ---- scale + mask + online softmax ----
        float tm0 = -1e30f, tm1 = -1e30f;
#pragma unroll
        for (int nt = 0; nt < 4; nt++) {
            int c = kv0 + nt * 8 + 2 * tig;
            float v0 = sfr[nt][0] * 0.125f;
            float v1 = sfr[nt][1] * 0.125f;
            float v2 = sfr[nt][2] * 0.125f;
            float v3 = sfr[nt][3] * 0.125f;
            if (domask) {
                if (c     > wrow)     v0 = -1e30f;
                if (c + 1 > wrow)     v1 = -1e30f;
                if (c     > wrow + 8) v2 = -1e30f;
                if (c + 1 > wrow + 8) v3 = -1e30f;
            }
            sfr[nt][0] = v0; sfr[nt][1] = v1; sfr[nt][2] = v2; sfr[nt][3] = v3;
            tm0 = fmaxf(tm0, fmaxf(v0, v1));
            tm1 = fmaxf(tm1, fmaxf(v2, v3));
        }
        tm0 = fmaxf(tm0, __shfl_xor_sync(0xffffffffu, tm0, 1));
        tm0 = fmaxf(tm0, __shfl_xor_sync(0xffffffffu, tm0, 2));
        tm1 = fmaxf(tm1, __shfl_xor_sync(0xffffffffu, tm1, 1));
        tm1 = fmaxf(tm1, __shfl_xor_sync(0xffffffffu, tm1, 2));

        float mn0 = fmaxf(m0, tm0), mn1 = fmaxf(m1, tm1);
        float a0 = __expf(m0 - mn0), a1 = __expf(m1 - mn1);
        float s0 = 0.0f, s1 = 0.0f;
#pragma unroll
        for (int nt = 0; nt < 4; nt++) {
            float p0 = __expf(sfr[nt][0] - mn0);
            float p1 = __expf(sfr[nt][1] - mn0);
            float p2 = __expf(sfr[nt][2] - mn1);
            float p3 = __expf(sfr[nt][3] - mn1);
            sfr[nt][0] = p0; sfr[nt][1] = p1; sfr[nt][2] = p2; sfr[nt][3] = p3;
            s0 += p0 + p1; s1 += p2 + p3;
        }
        s0 += __shfl_xor_sync(0xffffffffu, s0, 1);
        s0 += __shfl_xor_sync(0xffffffffu, s0, 2);
        s1 += __shfl_xor_sync(0xffffffffu, s1, 1);
        s1 += __shfl_xor_sync(0xffffffffu, s1, 2);
        l0 = l0 * a0 + s0; l1 = l1 * a1 + s1;
        m0 = mn0; m1 = mn1;
#pragma unroll
        for (int nt = 0; nt < 8; nt++) {
            oacc[nt][0] *= a0; oacc[nt][1] *= a0;
            oacc[nt][2] *= a1; oacc[nt][3] *= a1;
        }

        // ---- O += P V (3x tf32); P A-frags via shfl from S accum frags ----
#pragma unroll
        for (int ks = 0; ks < 4; ks++) {
            int srcA = (lid & ~3) | (tig >> 1);
            float x0 = __shfl_sync(0xffffffffu, sfr[ks][0], srcA);
            float x1 = __shfl_sync(0xffffffffu, sfr[ks][1], srcA);
            float x2 = __shfl_sync(0xffffffffu, sfr[ks][2], srcA);
            float x3 = __shfl_sync(0xffffffffu, sfr[ks][3], srcA);
            float y0 = __shfl_sync(0xffffffffu, sfr[ks][0], srcA + 2);
            float y1 = __shfl_sync(0xffffffffu, sfr[ks][1], srcA + 2);
            float y2 = __shfl_sync(0xffffffffu, sfr[ks][2], srcA + 2);
            float y3 = __shfl_sync(0xffffffffu, sfr[ks][3], srcA + 2);
            float p0 = (tig & 1) ? x1 : x0;   // P[gid][8ks+tig]
            float p1 = (tig & 1) ? x3 : x2;   // P[gid+8][8ks+tig]
            float p2 = (tig & 1) ? y1 : y0;   // P[gid][8ks+tig+4]
            float p3 = (tig & 1) ? y3 : y2;   // P[gid+8][8ks+tig+4]
            uint32_t ph[4] = { f2tf32(p0), f2tf32(p1), f2tf32(p2), f2tf32(p3) };
            uint32_t pl[4] = { f2tf32(p0 - __uint_as_float(ph[0])),
                               f2tf32(p1 - __uint_as_float(ph[1])),
                               f2tf32(p2 - __uint_as_float(ph[2])),
                               f2tf32(p3 - __uint_as_float(ph[3])) };
#pragma unroll
            for (int nt = 0; nt < 8; nt++) {
                int r0i = (ks * 8 + tig) * VP + nt * 8 + gid;
                int r1i = (ks * 8 + tig + 4) * VP + nt * 8 + gid;
                uint32_t BH[2] = { Vh[r0i], Vh[r1i] };
                uint32_t BL[2] = { Vl[r0i], Vl[r1i] };
                mma_tf32(oacc[nt], ph, BH);
                mma_tf32(oacc[nt], ph, BL);
                mma_tf32(oacc[nt], pl, BH);
            }
        }
    }

    // ---- epilogue ----
    float i0 = 1.0f / l0, i1 = 1.0f / l1;
    float* o0 = O + ((size_t)b * SS + wrow) * DM + h * 64;
    float* o1 = o0 + 8 * DM;
#pragma unroll
    for (int nt = 0; nt < 8; nt++) {
        *(float2*)(o0 + nt * 8 + 2 * tig) =
            make_float2(oacc[nt][0] * i0, oacc[nt][1] * i0);
        *(float2*)(o1 + nt * 8 + 2 * tig) =
            make_float2(oacc[nt][2] * i1, oacc[nt][3] * i1);
    }
}

// ---------------------------------------------------------------------------
extern "C" void kernel_launch(void* const* d_in, const int* in_sizes, int n_in,
                              void* d_out, int out_size)
{
    const float* x  = (const float*)d_in[0];
    const float* qw = (const float*)d_in[1];
    const float* kw = (const float*)d_in[2];
    const float* vw = (const float*)d_in[3];
    const float* ow = (const float*)d_in[4];
    float* out = (float*)d_out;

    float *q, *k, *v, *att;
    cudaGetSymbolAddress((void**)&q,   g_q);
    cudaGetSymbolAddress((void**)&k,   g_k);
    cudaGetSymbolAddress((void**)&v,   g_v);
    cudaGetSymbolAddress((void**)&att, g_att);

    dim3 gg(DM / 128, MM / 128);   // (8, 64) = 512 CTAs

    tgemm_kernel<<<gg, 256>>>(x, qw, q, 1);
    tgemm_kernel<<<gg, 256>>>(x, kw, k, 1);
    tgemm_kernel<<<gg, 256>>>(x, vw, v, 1);

    const int nrope = BB * NH * SS * 32;
    rope_kernel<<<nrope / 256, 256>>>(q);
    rope_kernel<<<nrope / 256, 256>>>(k);

    fattn_kernel<<<dim3(32, 64), 128>>>(q, k, v, att);

    tgemm_kernel<<<gg, 256>>>(att, ow, out, 0);
}